// round 12
// baseline (speedup 1.0000x reference)
#include <cuda_runtime.h>
#include <cstdint>
#include <cstddef>

// ============================================================
// Problem dims (fixed for this dataset)
// ============================================================
#define BCH 8192
#define D0  1024
#define D1  2048
#define D2  1024
#define FEAT 9                   // 8 spline basis + 1 silu
#define K0 (D0*FEAT)             // 9216
#define K1 (D1*FEAT)             // 18432

// ============================================================
// Scratch (static device globals — no runtime allocation)
// ============================================================
__device__ float g_A0[(size_t)BCH*K0];   // 302 MB
__device__ float g_W0[(size_t)D1 *K0];   // 75.5 MB
__device__ float g_H1[(size_t)BCH*D1];   // 67 MB
__device__ float g_A1[(size_t)BCH*K1];   // 604 MB
__device__ float g_W1[(size_t)D2 *K1];   // 75.5 MB

// ============================================================
// Helpers
// ============================================================
__device__ __forceinline__ float tf32r(float x) {
    asm("cvt.rna.tf32.f32 %0, %0;" : "+f"(x));
    return x;
}

__device__ __forceinline__ uint32_t smem_u32(const void* p) {
    uint32_t a;
    asm("{ .reg .u64 t; cvta.to.shared.u64 t, %1; cvt.u32.u64 %0, t; }" : "=r"(a) : "l"(p));
    return a;
}

__device__ __forceinline__ void cp16(uint32_t saddr, const void* gaddr) {
    asm volatile("cp.async.cg.shared.global [%0], [%1], 16;" :: "r"(saddr), "l"(gaddr));
}

// split v into tf32 hi + tf32 lo (3xTF32 trick)
__device__ __forceinline__ void tf32_split(float v, uint32_t& hi, uint32_t& lo) {
    float h = tf32r(v);
    float l = tf32r(v - h);
    hi = __float_as_uint(h);
    lo = __float_as_uint(l);
}

// ============================================================
// Prep kernels (store FULL fp32; split happens inside the GEMM)
// ============================================================

// Cox-de Boor (k=3), exact mirror of the reference recursion, + silu
__device__ __forceinline__ void kan_features(float x, const float* __restrict__ grid, float* f) {
    float t[12];
#pragma unroll
    for (int j = 0; j < 12; j++) t[j] = __ldg(grid + j);
    float Bv[11];
#pragma unroll
    for (int j = 0; j < 11; j++) Bv[j] = (x >= t[j] && x < t[j + 1]) ? 1.f : 0.f;
#pragma unroll
    for (int p = 1; p <= 3; p++) {
#pragma unroll
        for (int j = 0; j + p < 11; j++) {
            float left  = (x - t[j])         / (t[j + p]     - t[j]);
            float right = (t[j + p + 1] - x) / (t[j + p + 1] - t[j + 1]);
            Bv[j] = left * Bv[j] + right * Bv[j + 1];
        }
    }
#pragma unroll
    for (int c = 0; c < 8; c++) f[c] = Bv[c];
    f[8] = x / (1.f + expf(-x));   // silu
}

// which==0: X_ext -> g_A0 ; which==1: g_H1 -> g_A1
__global__ void prep_a_kernel(const float* __restrict__ X_ext,
                              const float* __restrict__ grid,
                              int which, int total) {
    const float* X = (which == 0) ? X_ext : g_H1;
    float*       A = (which == 0) ? g_A0  : g_A1;
    for (int e = blockIdx.x * blockDim.x + threadIdx.x; e < total;
         e += gridDim.x * blockDim.x) {
        float f[FEAT];
        kan_features(X[e], grid, f);
        float* a = A + (size_t)e * FEAT;
#pragma unroll
        for (int j = 0; j < FEAT; j++) a[j] = f[j];
    }
}

// which==0 -> g_W0 ; which==1 -> g_W1
__global__ void prep_w_kernel(const float* __restrict__ coef, const float* __restrict__ sb,
                              const float* __restrict__ sp, const float* __restrict__ mask,
                              int which, int total) {
    float* Wbase = (which == 0) ? g_W0 : g_W1;
    for (int e = blockIdx.x * blockDim.x + threadIdx.x; e < total;
         e += gridDim.x * blockDim.x) {
        float* W = Wbase + (size_t)e * FEAT;
        float m = mask[e];
        float s = sp[e] * m;
        const float* c = coef + (size_t)e * 8;
#pragma unroll
        for (int j = 0; j < 8; j++) W[j] = c[j] * s;
        W[8] = sb[e] * m;
    }
}

// ============================================================
// 3xTF32 mma.sync GEMM:  C[M,N] = A[M,K] * W[N,K]^T + bias
// BM=128, BN=128, BK=32, 256 threads (4x2 warps, 32x64 warp tile),
// 4-stage cp.async pipeline, padded SMEM (stride 36 floats).
// acc += Ah*Bh + Ah*Bl + Al*Bh   (fp32-grade accuracy)
// ============================================================
constexpr int BM = 128, BN = 128, BK = 32;
constexpr int STAGES      = 4;
constexpr int SROW        = 36;                    // floats per smem row (pad 32->36)
constexpr int TILE_FLOATS = 128 * SROW;            // one operand tile
constexpr int STG_FLOATS  = 2 * TILE_FLOATS;       // A + B
constexpr int GEMM_SMEM   = STAGES * STG_FLOATS * 4;   // 147456 B

__global__ void __launch_bounds__(256, 1)
kan_gemm_kernel(int which, const float* __restrict__ bias, float* __restrict__ Cout,
                int Ntot, int Ktot)
{
    extern __shared__ float smem[];

    const float* A = (which == 0) ? g_A0 : g_A1;
    const float* W = (which == 0) ? g_W0 : g_W1;
    float*       C = (which == 0) ? g_H1 : Cout;

    const int tid  = threadIdx.x;
    const int wid  = tid >> 5, lane = tid & 31;
    const int g    = lane >> 2, t = lane & 3;      // mma quad coords
    const int warp_m = wid & 3, warp_n = wid >> 2; // 4 x 2 warp grid

    // CTA swizzle: supergroups of 8 M-tiles so a wave shares A/B tiles in L2
    const int grid_n = Ntot / BN;
    const int GROUP  = 8;
    const int ppg    = GROUP * grid_n;
    const int pid    = blockIdx.x;
    const int mt0    = (pid / ppg) * GROUP + (pid % GROUP);
    const int nt0    = (pid % ppg) / GROUP;
    const int m0     = mt0 * BM;
    const int n0     = nt0 * BN;
    const int KI     = Ktot / BK;

    const uint32_t sbase = smem_u32(smem);
    const float* gA = A + (size_t)m0 * Ktot;
    const float* gB = W + (size_t)n0 * Ktot;

    auto load_stage = [&](int s, int kt) {
        uint32_t as = sbase + (uint32_t)(s * STG_FLOATS) * 4u;
        uint32_t bs = as + (uint32_t)TILE_FLOATS * 4u;
        const float* a = gA + (size_t)kt * BK;
        const float* b = gB + (size_t)kt * BK;
#pragma unroll
        for (int it = 0; it < 4; it++) {           // A: 128 rows x 8 x 16B
            int c = tid + it * 256;
            int r = c >> 3, ch = c & 7;
            cp16(as + (uint32_t)(r * SROW + ch * 4) * 4u, a + (size_t)r * Ktot + ch * 4);
        }
#pragma unroll
        for (int it = 0; it < 4; it++) {           // B: 128 rows x 8 x 16B
            int c = tid + it * 256;
            int r = c >> 3, ch = c & 7;
            cp16(bs + (uint32_t)(r * SROW + ch * 4) * 4u, b + (size_t)r * Ktot + ch * 4);
        }
        asm volatile("cp.async.commit_group;" ::: "memory");
    };

    float acc[2][8][4];
#pragma unroll
    for (int mt = 0; mt < 2; mt++)
#pragma unroll
        for (int nt = 0; nt < 8; nt++)
#pragma unroll
            for (int i = 0; i < 4; i++) acc[mt][nt][i] = 0.f;

    // prologue: 3 stages in flight
    for (int s = 0; s < 3; s++) load_stage(s, s);

#define MMA_TF32(d, a0, a1, a2, a3, b0, b1) \
    asm volatile( \
        "mma.sync.aligned.m16n8k8.row.col.f32.tf32.tf32.f32 " \
        "{%0,%1,%2,%3}, {%4,%5,%6,%7}, {%8,%9}, {%0,%1,%2,%3};" \
        : "+f"((d)[0]), "+f"((d)[1]), "+f"((d)[2]), "+f"((d)[3]) \
        : "r"(a0), "r"(a1), "r"(a2), "r"(a3), "r"(b0), "r"(b1))

    for (int ki = 0; ki < KI; ki++) {
        if (ki < KI - 2)        asm volatile("cp.async.wait_group 2;" ::: "memory");
        else if (ki == KI - 2)  asm volatile("cp.async.wait_group 1;" ::: "memory");
        else                    asm volatile("cp.async.wait_group 0;" ::: "memory");
        __syncthreads();   // stage ki visible to all; all warps past compute(ki-1)

        if (ki + 3 < KI) load_stage((ki + 3) & 3, ki + 3);  // overwrites stage (ki-1)&3: safe post-sync

        const float* As = smem + (size_t)(ki & 3) * STG_FLOATS;
        const float* Bs = As + TILE_FLOATS;

#pragma unroll
        for (int ks = 0; ks < 4; ks++) {
            const int k = ks * 8;
            uint32_t ah[2][4], al[2][4], bh[8][2], bl[8][2];
#pragma unroll
            for (int mt = 0; mt < 2; mt++) {
                const float* p = As + (warp_m * 32 + mt * 16 + g) * SROW + k + t;
                tf32_split(p[0],            ah[mt][0], al[mt][0]);
                tf32_split(p[8 * SROW],     ah[mt][1], al[mt][1]);
                tf32_split(p[4],            ah[mt][2], al[mt][2]);
                tf32_split(p[8 * SROW + 4], ah[mt][3], al[mt][3]);
            }
#pragma unroll
            for (int nt = 0; nt < 8; nt++) {
                const float* p = Bs + (warp_n * 64 + nt * 8 + g) * SROW + k + t;
                tf32_split(p[0], bh[nt][0], bl[nt][0]);
                tf32_split(p[4], bh[nt][1], bl[nt][1]);
            }
#pragma unroll
            for (int mt = 0; mt < 2; mt++)
#pragma unroll
                for (int nt = 0; nt < 8; nt++) {
                    // hi*lo + lo*hi first (small terms), hi*hi last
                    MMA_TF32(acc[mt][nt], ah[mt][0], ah[mt][1], ah[mt][2], ah[mt][3],
                             bl[nt][0], bl[nt][1]);
                    MMA_TF32(acc[mt][nt], al[mt][0], al[mt][1], al[mt][2], al[mt][3],
                             bh[nt][0], bh[nt][1]);
                    MMA_TF32(acc[mt][nt], ah[mt][0], ah[mt][1], ah[mt][2], ah[mt][3],
                             bh[nt][0], bh[nt][1]);
                }
        }
    }

    // ---- epilogue: direct float2 stores + bias ----
#pragma unroll
    for (int mt = 0; mt < 2; mt++) {
        const int r0 = m0 + warp_m * 32 + mt * 16 + g;
#pragma unroll
        for (int nt = 0; nt < 8; nt++) {
            const int col = n0 + warp_n * 64 + nt * 8 + 2 * t;
            const float2 b2 = *(const float2*)(bias + col);
            float2 v0 = make_float2(acc[mt][nt][0] + b2.x, acc[mt][nt][1] + b2.y);
            float2 v1 = make_float2(acc[mt][nt][2] + b2.x, acc[mt][nt][3] + b2.y);
            *(float2*)(C + (size_t)r0 * Ntot + col)       = v0;
            *(float2*)(C + (size_t)(r0 + 8) * Ntot + col) = v1;
        }
    }
#undef MMA_TF32
}

// ============================================================
// Launch
// ============================================================
extern "C" void kernel_launch(void* const* d_in, const int* in_sizes, int n_in,
                              void* d_out, int out_size) {
    const float* x     = (const float*)d_in[0];
    const float* coef0 = (const float*)d_in[1];
    const float* sb0   = (const float*)d_in[2];
    const float* sp0   = (const float*)d_in[3];
    const float* mask0 = (const float*)d_in[4];
    const float* bias0 = (const float*)d_in[5];
    const float* coef1 = (const float*)d_in[6];
    const float* sb1   = (const float*)d_in[7];
    const float* sp1   = (const float*)d_in[8];
    const float* mask1 = (const float*)d_in[9];
    const float* bias1 = (const float*)d_in[10];
    const float* grid  = (const float*)d_in[11];
    float* out = (float*)d_out;

    cudaFuncSetAttribute(kan_gemm_kernel, cudaFuncAttributeMaxDynamicSharedMemorySize, GEMM_SMEM);

    // weight prep
    prep_w_kernel<<<2048, 512>>>(coef0, sb0, sp0, mask0, 0, D1 * D0);
    prep_w_kernel<<<2048, 512>>>(coef1, sb1, sp1, mask1, 1, D2 * D1);
    // layer 0 features
    prep_a_kernel<<<2048, 512>>>(x, grid, 0, BCH * D0);
    // GEMM1: H1 = A0 * W0^T + bias0   (M=8192, N=2048, K=9216)
    {
        int blocks = (BCH / BM) * (D1 / BN);    // 64 * 16 = 1024
        kan_gemm_kernel<<<blocks, 256, GEMM_SMEM>>>(0, bias0, nullptr, D1, K0);
    }
    // layer 1 features
    prep_a_kernel<<<4096, 512>>>(nullptr, grid, 1, BCH * D1);
    // GEMM2: out = A1 * W1^T + bias1  (M=8192, N=1024, K=18432)
    {
        int blocks = (BCH / BM) * (D2 / BN);    // 64 * 8 = 512
        kan_gemm_kernel<<<blocks, 256, GEMM_SMEM>>>(1, bias1, out, D2, K1);
    }
}

// round 13
// speedup vs baseline: 1.6499x; 1.6499x over previous
#include <cuda_runtime.h>
#include <cuda_bf16.h>
#include <cstdint>
#include <cstddef>

// ============================================================
// Problem dims (fixed for this dataset)
// ============================================================
#define BCH 8192
#define D0  1024
#define D1  2048
#define D2  1024
#define FEAT 9                    // 8 spline basis + 1 silu
#define K0 (D0*FEAT)              // 9216
#define K1 (D1*FEAT)              // 18432
#define KP0 (K0*3)                // 27648  (bf16x3 interleaved)
#define KP1 (K1*3)                // 55296

// ============================================================
// Scratch (static device globals — no runtime allocation)
// A3 slots per source k: (ah, al, ah) ; W3 slots: (wh, wh, wl)
// sum_s A3*W3 = ah*wh + al*wh + ah*wl   (3xBF16, drops al*wl ~2^-18)
// ============================================================
__device__ __nv_bfloat16 g_A0[(size_t)BCH*KP0];   // 453 MB
__device__ __nv_bfloat16 g_W0[(size_t)D1 *KP0];   // 113 MB
__device__ float         g_H1[(size_t)BCH*D1];    // 67 MB
__device__ __nv_bfloat16 g_A1[(size_t)BCH*KP1];   // 906 MB
__device__ __nv_bfloat16 g_W1[(size_t)D2 *KP1];   // 113 MB

// ============================================================
// Helpers
// ============================================================
__device__ __forceinline__ uint32_t smem_u32(const void* p) {
    uint32_t a;
    asm("{ .reg .u64 t; cvta.to.shared.u64 t, %1; cvt.u32.u64 %0, t; }" : "=r"(a) : "l"(p));
    return a;
}

__device__ __forceinline__ void cp16(uint32_t saddr, const void* gaddr) {
    asm volatile("cp.async.cg.shared.global [%0], [%1], 16;" :: "r"(saddr), "l"(gaddr));
}

// split v into bf16 hi + bf16 lo
__device__ __forceinline__ void bf16_split(float v, __nv_bfloat16& h, __nv_bfloat16& l) {
    h = __float2bfloat16(v);
    l = __float2bfloat16(v - __bfloat162float(h));
}

// ============================================================
// Prep kernels: compute features / weights, write bf16x3 planes
// ============================================================

// Cox-de Boor (k=3), exact mirror of the reference recursion, + silu
__device__ __forceinline__ void kan_features(float x, const float* __restrict__ grid, float* f) {
    float t[12];
#pragma unroll
    for (int j = 0; j < 12; j++) t[j] = __ldg(grid + j);
    float Bv[11];
#pragma unroll
    for (int j = 0; j < 11; j++) Bv[j] = (x >= t[j] && x < t[j + 1]) ? 1.f : 0.f;
#pragma unroll
    for (int p = 1; p <= 3; p++) {
#pragma unroll
        for (int j = 0; j + p < 11; j++) {
            float left  = (x - t[j])         / (t[j + p]     - t[j]);
            float right = (t[j + p + 1] - x) / (t[j + p + 1] - t[j + 1]);
            Bv[j] = left * Bv[j] + right * Bv[j + 1];
        }
    }
#pragma unroll
    for (int c = 0; c < 8; c++) f[c] = Bv[c];
    f[8] = x / (1.f + expf(-x));   // silu
}

// which==0: X_ext -> g_A0 ; which==1: g_H1 -> g_A1
__global__ void prep_a_kernel(const float* __restrict__ X_ext,
                              const float* __restrict__ grid,
                              int which, int total) {
    const float* X = (which == 0) ? X_ext : g_H1;
    __nv_bfloat16* A = (which == 0) ? g_A0 : g_A1;
    for (int e = blockIdx.x * blockDim.x + threadIdx.x; e < total;
         e += gridDim.x * blockDim.x) {
        float f[FEAT];
        kan_features(X[e], grid, f);
        __nv_bfloat16* a = A + (size_t)e * (FEAT * 3);
#pragma unroll
        for (int j = 0; j < FEAT; j++) {
            __nv_bfloat16 h, l;
            bf16_split(f[j], h, l);
            a[3*j + 0] = h;   // pairs with wh
            a[3*j + 1] = l;   // pairs with wh
            a[3*j + 2] = h;   // pairs with wl
        }
    }
}

// which==0 -> g_W0 ; which==1 -> g_W1
__global__ void prep_w_kernel(const float* __restrict__ coef, const float* __restrict__ sb,
                              const float* __restrict__ sp, const float* __restrict__ mask,
                              int which, int total) {
    __nv_bfloat16* Wbase = (which == 0) ? g_W0 : g_W1;
    for (int e = blockIdx.x * blockDim.x + threadIdx.x; e < total;
         e += gridDim.x * blockDim.x) {
        __nv_bfloat16* W = Wbase + (size_t)e * (FEAT * 3);
        float m = mask[e];
        float s = sp[e] * m;
        const float* c = coef + (size_t)e * 8;
#pragma unroll
        for (int j = 0; j < FEAT; j++) {
            float v = (j < 8) ? c[j] * s : sb[e] * m;
            __nv_bfloat16 h, l;
            bf16_split(v, h, l);
            W[3*j + 0] = h;   // pairs with ah
            W[3*j + 1] = h;   // pairs with al
            W[3*j + 2] = l;   // pairs with ah
        }
    }
}

// ============================================================
// bf16 mma.sync GEMM over interleaved K' = 3K:
//   C[M,N] = A3[M,K'] * W3[N,K']^T + bias
// BM=128, BN=128, BK'=64 bf16 (128B rows, padded to 144B),
// 256 threads (4x2 warps, 32x64 warp tile), 4-stage cp.async.
// ============================================================
constexpr int BM = 128, BN = 128, BKP = 64;
constexpr int STAGES     = 4;
constexpr int ROW_BYTES  = 144;                   // 128B data + 16B pad (36 words: 36%32=4 -> conflict-free)
constexpr int ROW_WORDS  = 36;
constexpr int TILE_BYTES = 128 * ROW_BYTES;       // 18432
constexpr int STG_BYTES  = 2 * TILE_BYTES;        // 36864
constexpr int GEMM_SMEM  = STAGES * STG_BYTES;    // 147456

__global__ void __launch_bounds__(256, 1)
kan_gemm_kernel(int which, const float* __restrict__ bias, float* __restrict__ Cout,
                int Ntot, int Kp)
{
    extern __shared__ char smem[];

    const __nv_bfloat16* A = (which == 0) ? g_A0 : g_A1;
    const __nv_bfloat16* W = (which == 0) ? g_W0 : g_W1;
    float*               C = (which == 0) ? g_H1 : Cout;

    const int tid  = threadIdx.x;
    const int wid  = tid >> 5, lane = tid & 31;
    const int g    = lane >> 2, t = lane & 3;      // mma quad coords
    const int warp_m = wid & 3, warp_n = wid >> 2; // 4 x 2 warp grid

    // CTA swizzle: supergroups of 8 M-tiles so a wave shares A/B tiles in L2
    const int grid_n = Ntot / BN;
    const int GROUP  = 8;
    const int ppg    = GROUP * grid_n;
    const int pid    = blockIdx.x;
    const int mt0    = (pid / ppg) * GROUP + (pid % GROUP);
    const int nt0    = (pid % ppg) / GROUP;
    const int m0     = mt0 * BM;
    const int n0     = nt0 * BN;
    const int KI     = Kp / BKP;

    const uint32_t sbase = smem_u32(smem);
    const __nv_bfloat16* gA = A + (size_t)m0 * Kp;
    const __nv_bfloat16* gB = W + (size_t)n0 * Kp;

    auto load_stage = [&](int s, int kt) {
        uint32_t as = sbase + (uint32_t)(s * STG_BYTES);
        uint32_t bs = as + (uint32_t)TILE_BYTES;
        const __nv_bfloat16* a = gA + (size_t)kt * BKP;
        const __nv_bfloat16* b = gB + (size_t)kt * BKP;
#pragma unroll
        for (int it = 0; it < 4; it++) {           // A: 128 rows x 8 x 16B
            int c = tid + it * 256;
            int r = c >> 3, ch = c & 7;
            cp16(as + (uint32_t)(r * ROW_BYTES + ch * 16), a + (size_t)r * Kp + ch * 8);
        }
#pragma unroll
        for (int it = 0; it < 4; it++) {           // B: 128 rows x 8 x 16B
            int c = tid + it * 256;
            int r = c >> 3, ch = c & 7;
            cp16(bs + (uint32_t)(r * ROW_BYTES + ch * 16), b + (size_t)r * Kp + ch * 8);
        }
        asm volatile("cp.async.commit_group;" ::: "memory");
    };

    float acc[2][8][4];
#pragma unroll
    for (int mt = 0; mt < 2; mt++)
#pragma unroll
        for (int nt = 0; nt < 8; nt++)
#pragma unroll
            for (int i = 0; i < 4; i++) acc[mt][nt][i] = 0.f;

    // prologue: 3 stages in flight
    for (int s = 0; s < 3; s++) load_stage(s, s);

    for (int ki = 0; ki < KI; ki++) {
        if (ki < KI - 2)        asm volatile("cp.async.wait_group 2;" ::: "memory");
        else if (ki == KI - 2)  asm volatile("cp.async.wait_group 1;" ::: "memory");
        else                    asm volatile("cp.async.wait_group 0;" ::: "memory");
        __syncthreads();   // stage ki visible; all warps past compute(ki-1)

        if (ki + 3 < KI) load_stage((ki + 3) & 3, ki + 3);  // overwrites stage (ki-1)&3: safe post-sync

        const uint32_t* As32 = (const uint32_t*)(smem + (size_t)(ki & 3) * STG_BYTES);
        const uint32_t* Bs32 = As32 + TILE_BYTES / 4;

#pragma unroll
        for (int ks = 0; ks < 4; ks++) {           // 4 x k16 steps over BK'=64
            uint32_t a[2][4], b[8][2];
#pragma unroll
            for (int mt = 0; mt < 2; mt++) {
                const uint32_t* p = As32 + (warp_m * 32 + mt * 16 + g) * ROW_WORDS + 8 * ks + t;
                a[mt][0] = p[0];
                a[mt][1] = p[8 * ROW_WORDS];
                a[mt][2] = p[4];
                a[mt][3] = p[8 * ROW_WORDS + 4];
            }
#pragma unroll
            for (int nt = 0; nt < 8; nt++) {
                const uint32_t* p = Bs32 + (warp_n * 64 + nt * 8 + g) * ROW_WORDS + 8 * ks + t;
                b[nt][0] = p[0];
                b[nt][1] = p[4];
            }
#pragma unroll
            for (int mt = 0; mt < 2; mt++)
#pragma unroll
                for (int nt = 0; nt < 8; nt++)
                    asm volatile(
                        "mma.sync.aligned.m16n8k16.row.col.f32.bf16.bf16.f32 "
                        "{%0,%1,%2,%3}, {%4,%5,%6,%7}, {%8,%9}, {%0,%1,%2,%3};"
                        : "+f"(acc[mt][nt][0]), "+f"(acc[mt][nt][1]),
                          "+f"(acc[mt][nt][2]), "+f"(acc[mt][nt][3])
                        : "r"(a[mt][0]), "r"(a[mt][1]), "r"(a[mt][2]), "r"(a[mt][3]),
                          "r"(b[nt][0]), "r"(b[nt][1]));
        }
    }

    // ---- epilogue: direct float2 stores + bias ----
#pragma unroll
    for (int mt = 0; mt < 2; mt++) {
        const int r0 = m0 + warp_m * 32 + mt * 16 + g;
#pragma unroll
        for (int nt = 0; nt < 8; nt++) {
            const int col = n0 + warp_n * 64 + nt * 8 + 2 * t;
            const float2 b2 = *(const float2*)(bias + col);
            float2 v0 = make_float2(acc[mt][nt][0] + b2.x, acc[mt][nt][1] + b2.y);
            float2 v1 = make_float2(acc[mt][nt][2] + b2.x, acc[mt][nt][3] + b2.y);
            *(float2*)(C + (size_t)r0 * Ntot + col)       = v0;
            *(float2*)(C + (size_t)(r0 + 8) * Ntot + col) = v1;
        }
    }
}

// ============================================================
// Launch
// ============================================================
extern "C" void kernel_launch(void* const* d_in, const int* in_sizes, int n_in,
                              void* d_out, int out_size) {
    const float* x     = (const float*)d_in[0];
    const float* coef0 = (const float*)d_in[1];
    const float* sb0   = (const float*)d_in[2];
    const float* sp0   = (const float*)d_in[3];
    const float* mask0 = (const float*)d_in[4];
    const float* bias0 = (const float*)d_in[5];
    const float* coef1 = (const float*)d_in[6];
    const float* sb1   = (const float*)d_in[7];
    const float* sp1   = (const float*)d_in[8];
    const float* mask1 = (const float*)d_in[9];
    const float* bias1 = (const float*)d_in[10];
    const float* grid  = (const float*)d_in[11];
    float* out = (float*)d_out;

    cudaFuncSetAttribute(kan_gemm_kernel, cudaFuncAttributeMaxDynamicSharedMemorySize, GEMM_SMEM);

    // weight prep (bf16x3 planes)
    prep_w_kernel<<<2048, 512>>>(coef0, sb0, sp0, mask0, 0, D1 * D0);
    prep_w_kernel<<<2048, 512>>>(coef1, sb1, sp1, mask1, 1, D2 * D1);
    // layer 0 features
    prep_a_kernel<<<2048, 512>>>(x, grid, 0, BCH * D0);
    // GEMM1: H1 = A0 * W0^T + bias0   (M=8192, N=2048, K'=27648)
    {
        int blocks = (BCH / BM) * (D1 / BN);    // 1024
        kan_gemm_kernel<<<blocks, 256, GEMM_SMEM>>>(0, bias0, nullptr, D1, KP0);
    }
    // layer 1 features
    prep_a_kernel<<<4096, 512>>>(nullptr, grid, 1, BCH * D1);
    // GEMM2: out = A1 * W1^T + bias1  (M=8192, N=1024, K'=55296)
    {
        int blocks = (BCH / BM) * (D2 / BN);    // 512
        kan_gemm_kernel<<<blocks, 256, GEMM_SMEM>>>(1, bias1, out, D2, KP1);
    }
}